// round 3
// baseline (speedup 1.0000x reference)
#include <cuda_runtime.h>
#include <cstdint>

#define N_NODES 50000
#define N_EDGES 800000
#define IN_F 256
#define HEADS 4
#define OUT_F 64
#define HF 256            // HEADS * OUT_F
#define NEG_SLOPE 0.2f

// ---------------- scratch (static device allocations; no cudaMalloc) --------
__device__ float g_h[(size_t)N_NODES * HF];      // 51.2 MB  projected features
__device__ float g_asrc[N_NODES * HEADS];
__device__ float g_adst[N_NODES * HEADS];
__device__ int   g_deg[N_NODES];
__device__ int   g_off[N_NODES + 1];
__device__ int   g_cursor[N_NODES];
__device__ int   g_csr[N_EDGES];                 // src ids grouped by dst

// ---------------- packed f32x2 helpers (Blackwell dual-FP32 pipe) -----------
__device__ __forceinline__ unsigned long long pk2(float lo, float hi) {
    unsigned long long r;
    asm("mov.b64 %0, {%1,%2};" : "=l"(r) : "f"(lo), "f"(hi));
    return r;
}
__device__ __forceinline__ void upk2(unsigned long long v, float& lo, float& hi) {
    asm("mov.b64 {%0,%1}, %2;" : "=f"(lo), "=f"(hi) : "l"(v));
}
#define FMA2(d, a, b) asm("fma.rn.f32x2 %0, %1, %2, %0;" : "+l"(d) : "l"(a), "l"(b))

// ---------------- GEMM: g_h = x @ W  (fp32, f32x2 FMA) ----------------------
#define BM 128
#define BN 64
#define BK 16
#define APAD 132   // pad to reduce STS bank conflicts; keeps 16B alignment

__global__ __launch_bounds__(256) void gemm_kernel(const float* __restrict__ A,
                                                   const float* __restrict__ B) {
    __shared__ __align__(16) float  As[BK][APAD];   // stored [k][m]
    __shared__ float4 Bs[BK][BN / 4];               // stored [k][n/4]

    const int tid = threadIdx.x;
    const int tx = tid & 15;       // 16 col groups * 4 cols
    const int ty = tid >> 4;       // 16 row groups * 8 rows
    const int mb = blockIdx.x * BM;
    const int nb = blockIdx.y * BN;

    unsigned long long acc[16];    // 4 row-pairs x 4 cols, each (row2r, row2r+1)
#pragma unroll
    for (int i = 0; i < 16; i++) acc[i] = 0ULL;

    for (int kt = 0; kt < IN_F / BK; kt++) {
        // load A tile: 128 rows x 16 cols = 512 float4, 2 per thread
#pragma unroll
        for (int i = 0; i < 2; i++) {
            int j = tid + i * 256;
            int r = j >> 2;
            int kc = (j & 3) << 2;
            int grow = mb + r;
            float4 v = make_float4(0.f, 0.f, 0.f, 0.f);
            if (grow < N_NODES)
                v = *(const float4*)(A + (size_t)grow * IN_F + kt * BK + kc);
            As[kc][r] = v.x; As[kc + 1][r] = v.y;
            As[kc + 2][r] = v.z; As[kc + 3][r] = v.w;
        }
        // load B tile: 16 rows x 64 cols = 256 float4, 1 per thread
        {
            int r = tid >> 4, c4 = tid & 15;
            Bs[r][c4] = *(const float4*)(B + (size_t)(kt * BK + r) * HF + nb + c4 * 4);
        }
        __syncthreads();

#pragma unroll
        for (int k = 0; k < BK; k++) {
            float4 a0 = *(const float4*)&As[k][ty * 8];       // broadcast reads
            float4 a1 = *(const float4*)&As[k][ty * 8 + 4];
            float4 b  = Bs[k][tx];
            unsigned long long A01 = pk2(a0.x, a0.y);
            unsigned long long A23 = pk2(a0.z, a0.w);
            unsigned long long A45 = pk2(a1.x, a1.y);
            unsigned long long A67 = pk2(a1.z, a1.w);
            float bc[4] = {b.x, b.y, b.z, b.w};
#pragma unroll
            for (int c = 0; c < 4; c++) {
                unsigned long long bb = pk2(bc[c], bc[c]);
                FMA2(acc[0  + c], A01, bb);
                FMA2(acc[4  + c], A23, bb);
                FMA2(acc[8  + c], A45, bb);
                FMA2(acc[12 + c], A67, bb);
            }
        }
        __syncthreads();
    }

    // store: acc[rp*4+c] = rows (ty*8 + 2rp, +1), cols nb + tx*4 + c
#pragma unroll
    for (int rp = 0; rp < 4; rp++) {
        float lo[4], hi[4];
#pragma unroll
        for (int c = 0; c < 4; c++) upk2(acc[rp * 4 + c], lo[c], hi[c]);
        int r0 = mb + ty * 8 + rp * 2;
        int col = nb + tx * 4;
        if (r0 < N_NODES)
            *(float4*)(g_h + (size_t)r0 * HF + col) = make_float4(lo[0], lo[1], lo[2], lo[3]);
        if (r0 + 1 < N_NODES)
            *(float4*)(g_h + (size_t)(r0 + 1) * HF + col) = make_float4(hi[0], hi[1], hi[2], hi[3]);
    }
}

// ---------------- per-node attention halves: a_src, a_dst -------------------
__global__ void att_kernel(const float* __restrict__ att_s,
                           const float* __restrict__ att_d) {
    int gw = (blockIdx.x * blockDim.x + threadIdx.x) >> 5;
    int lane = threadIdx.x & 31;
    if (gw >= N_NODES) return;
    const float* hr = g_h + (size_t)gw * HF;
#pragma unroll
    for (int hd = 0; hd < HEADS; hd++) {
        float v0 = hr[hd * 64 + lane];
        float v1 = hr[hd * 64 + 32 + lane];
        float s = v0 * att_s[hd * 64 + lane] + v1 * att_s[hd * 64 + 32 + lane];
        float d = v0 * att_d[hd * 64 + lane] + v1 * att_d[hd * 64 + 32 + lane];
#pragma unroll
        for (int o = 16; o; o >>= 1) {
            s += __shfl_xor_sync(0xffffffffu, s, o);
            d += __shfl_xor_sync(0xffffffffu, d, o);
        }
        if (lane == 0) {
            g_asrc[gw * HEADS + hd] = s;
            g_adst[gw * HEADS + hd] = d;
        }
    }
}

// ---------------- CSR build (edge_index is int32: JAX x64 is disabled) ------
__global__ void zero_deg_kernel() {
    int i = blockIdx.x * blockDim.x + threadIdx.x;
    if (i < N_NODES) g_deg[i] = 0;
}

__global__ void hist_kernel(const int* __restrict__ ei) {
    int e = blockIdx.x * blockDim.x + threadIdx.x;
    if (e >= N_EDGES) return;
    int d = ei[N_EDGES + e];
    if ((unsigned)d < N_NODES) atomicAdd(&g_deg[d], 1);
}

__global__ __launch_bounds__(1024) void scan_kernel() {
    __shared__ int tmp[1024];
    const int tid = threadIdx.x;
    const int CH = (N_NODES + 1023) / 1024;   // 49
    int start = tid * CH;
    int end = start + CH; if (end > N_NODES) end = N_NODES;
    int s = 0;
    for (int i = start; i < end; i++) s += g_deg[i];
    tmp[tid] = s;
    __syncthreads();
    for (int off = 1; off < 1024; off <<= 1) {
        int v = tmp[tid];
        if (tid >= off) v += tmp[tid - off];
        __syncthreads();
        tmp[tid] = v;
        __syncthreads();
    }
    int run = (tid == 0) ? 0 : tmp[tid - 1];
    for (int i = start; i < end; i++) {
        g_off[i] = run;
        g_cursor[i] = run;
        run += g_deg[i];
    }
    if (tid == 0) g_off[N_NODES] = tmp[1023];
}

__global__ void scatter_kernel(const int* __restrict__ ei) {
    int e = blockIdx.x * blockDim.x + threadIdx.x;
    if (e >= N_EDGES) return;
    int s = ei[e];
    int d = ei[N_EDGES + e];
    if ((unsigned)d >= N_NODES || (unsigned)s >= N_NODES) return;
    int pos = atomicAdd(&g_cursor[d], 1);
    g_csr[pos] = s;
}

// Canonicalize each segment (odd-even transposition sort, warp per node) so
// the accumulation order — and thus the fp32 output bits — is deterministic
// even though the atomic scatter order is not.
__global__ void sortseg_kernel() {
    int gw = (blockIdx.x * blockDim.x + threadIdx.x) >> 5;
    int lane = threadIdx.x & 31;
    if (gw >= N_NODES) return;
    int lo = g_off[gw], hi = g_off[gw + 1];
    int len = hi - lo;
    if (len < 2) return;
    for (int pass = 0; pass < len; pass++) {
        int start = lo + (pass & 1);
        for (int i = start + 2 * lane; i + 1 < hi; i += 64) {
            int a = g_csr[i], b = g_csr[i + 1];
            if (a > b) { g_csr[i] = b; g_csr[i + 1] = a; }
        }
        __syncwarp();
    }
}

// ---------------- aggregation: online softmax, warp per (node, head) --------
__global__ __launch_bounds__(256) void agg_kernel(const float* __restrict__ bias,
                                                  float* __restrict__ out) {
    int gw = (blockIdx.x * blockDim.x + threadIdx.x) >> 5;
    int lane = threadIdx.x & 31;
    if (gw >= N_NODES * HEADS) return;
    int n = gw >> 2;
    int hd = gw & 3;

    float adn = g_adst[n * HEADS + hd];

    // seed with the self-loop (s = n): deterministic first element
    float e0 = g_asrc[n * HEADS + hd] + adn;
    e0 = (e0 > 0.f) ? e0 : NEG_SLOPE * e0;
    float m = e0;
    float ssum = 1.0f;
    const float* hrow = g_h + (size_t)n * HF + hd * 64;
    float acc0 = hrow[lane];
    float acc1 = hrow[lane + 32];

    int lo = g_off[n], hi = g_off[n + 1];
    for (int j = lo; j < hi; j++) {
        int s = g_csr[j];
        float e = g_asrc[s * HEADS + hd] + adn;
        e = (e > 0.f) ? e : NEG_SLOPE * e;
        const float* hs = g_h + (size_t)s * HF + hd * 64;
        float v0 = hs[lane];
        float v1 = hs[lane + 32];
        if (e > m) {                       // warp-uniform branch
            float sc = __expf(m - e);
            ssum *= sc; acc0 *= sc; acc1 *= sc;
            m = e;
        }
        float w = __expf(e - m);
        ssum += w;
        acc0 += w * v0;
        acc1 += w * v1;
    }

    float inv = 1.0f / ssum;
    int col = hd * 64 + lane;
    out[(size_t)n * HF + col]      = acc0 * inv + bias[col];
    out[(size_t)n * HF + col + 32] = acc1 * inv + bias[col + 32];
}

// ---------------- launch ----------------------------------------------------
extern "C" void kernel_launch(void* const* d_in, const int* in_sizes, int n_in,
                              void* d_out, int out_size) {
    const float* x     = (const float*)d_in[0];
    const int*   ei    = (const int*)d_in[1];       // int32: JAX x64 disabled
    const float* W     = (const float*)d_in[2];
    const float* att_s = (const float*)d_in[3];
    const float* att_d = (const float*)d_in[4];
    const float* bias  = (const float*)d_in[5];
    float*       out   = (float*)d_out;
    (void)in_sizes; (void)n_in; (void)out_size;

    gemm_kernel<<<dim3((N_NODES + BM - 1) / BM, HF / BN), 256>>>(x, W);
    att_kernel<<<(N_NODES * 32 + 255) / 256, 256>>>(att_s, att_d);
    zero_deg_kernel<<<(N_NODES + 255) / 256, 256>>>();
    hist_kernel<<<(N_EDGES + 255) / 256, 256>>>(ei);
    scan_kernel<<<1, 1024>>>();
    scatter_kernel<<<(N_EDGES + 255) / 256, 256>>>(ei);
    sortseg_kernel<<<(N_NODES * 32 + 255) / 256, 256>>>();
    agg_kernel<<<(N_NODES * HEADS * 32 + 255) / 256, 256>>>(bias, out);
}

// round 4
// speedup vs baseline: 1.1959x; 1.1959x over previous
#include <cuda_runtime.h>
#include <cstdint>

#define N_NODES 50000
#define N_EDGES 800000
#define IN_F 256
#define HEADS 4
#define OUT_F 64
#define HF 256            // HEADS * OUT_F
#define NEG_SLOPE 0.2f

// ---------------- scratch (static device allocations; no cudaMalloc) --------
__device__ float g_h[(size_t)N_NODES * HF];      // 51.2 MB  projected features
__device__ float g_asrc[N_NODES * HEADS];
__device__ float g_adst[N_NODES * HEADS];
__device__ int   g_deg[N_NODES];
__device__ int   g_off[N_NODES + 1];
__device__ int   g_cursor[N_NODES];
__device__ int   g_csr[N_EDGES];                 // src ids grouped by dst

// ---------------- packed f32x2 helpers (Blackwell dual-FP32 pipe) -----------
__device__ __forceinline__ unsigned long long pk2(float lo, float hi) {
    unsigned long long r;
    asm("mov.b64 %0, {%1,%2};" : "=l"(r) : "f"(lo), "f"(hi));
    return r;
}
__device__ __forceinline__ void upk2(unsigned long long v, float& lo, float& hi) {
    asm("mov.b64 {%0,%1}, %2;" : "=f"(lo), "=f"(hi) : "l"(v));
}
#define FMA2(d, a, b) asm("fma.rn.f32x2 %0, %1, %2, %0;" : "+l"(d) : "l"(a), "l"(b))

// ------- GEMM: g_h = x @ W  (fp32, f32x2 FMA) + fused a_src/a_dst epilogue --
// grid.y block = one head (BN = 64 = OUT_F), so each block holds the complete
// head dot-product contributions for its 128 rows -> reduce over the 16-lane
// tx groups and write g_asrc/g_adst directly. Kills the separate att pass.
#define BM 128
#define BN 64
#define BK 16
#define APAD 132   // pad to reduce STS bank conflicts; keeps 16B alignment

__global__ __launch_bounds__(256) void gemm_kernel(const float* __restrict__ A,
                                                   const float* __restrict__ B,
                                                   const float* __restrict__ att_s,
                                                   const float* __restrict__ att_d) {
    __shared__ __align__(16) float  As[BK][APAD];   // stored [k][m]
    __shared__ float4 Bs[BK][BN / 4];               // stored [k][n/4]

    const int tid = threadIdx.x;
    const int tx = tid & 15;       // 16 col groups * 4 cols
    const int ty = tid >> 4;       // 16 row groups * 8 rows
    const int mb = blockIdx.x * BM;
    const int hd = blockIdx.y;     // head index; nb = hd*64
    const int nb = hd * BN;

    unsigned long long acc[16];    // 4 row-pairs x 4 cols, each (row2r, row2r+1)
#pragma unroll
    for (int i = 0; i < 16; i++) acc[i] = 0ULL;

    for (int kt = 0; kt < IN_F / BK; kt++) {
        // load A tile: 128 rows x 16 cols = 512 float4, 2 per thread
#pragma unroll
        for (int i = 0; i < 2; i++) {
            int j = tid + i * 256;
            int r = j >> 2;
            int kc = (j & 3) << 2;
            int grow = mb + r;
            float4 v = make_float4(0.f, 0.f, 0.f, 0.f);
            if (grow < N_NODES)
                v = *(const float4*)(A + (size_t)grow * IN_F + kt * BK + kc);
            As[kc][r] = v.x; As[kc + 1][r] = v.y;
            As[kc + 2][r] = v.z; As[kc + 3][r] = v.w;
        }
        // load B tile: 16 rows x 64 cols = 256 float4, 1 per thread
        {
            int r = tid >> 4, c4 = tid & 15;
            Bs[r][c4] = *(const float4*)(B + (size_t)(kt * BK + r) * HF + nb + c4 * 4);
        }
        __syncthreads();

#pragma unroll
        for (int k = 0; k < BK; k++) {
            float4 a0 = *(const float4*)&As[k][ty * 8];       // broadcast reads
            float4 a1 = *(const float4*)&As[k][ty * 8 + 4];
            float4 b  = Bs[k][tx];
            unsigned long long A01 = pk2(a0.x, a0.y);
            unsigned long long A23 = pk2(a0.z, a0.w);
            unsigned long long A45 = pk2(a1.x, a1.y);
            unsigned long long A67 = pk2(a1.z, a1.w);
            float bc[4] = {b.x, b.y, b.z, b.w};
#pragma unroll
            for (int c = 0; c < 4; c++) {
                unsigned long long bb = pk2(bc[c], bc[c]);
                FMA2(acc[0  + c], A01, bb);
                FMA2(acc[4  + c], A23, bb);
                FMA2(acc[8  + c], A45, bb);
                FMA2(acc[12 + c], A67, bb);
            }
        }
        __syncthreads();
    }

    // attention weight slices for this thread's 4 columns (fixed per tx)
    const float4 ws = *(const float4*)(att_s + hd * OUT_F + tx * 4);
    const float4 wd = *(const float4*)(att_d + hd * OUT_F + tx * 4);

    // store + fused attention dots
#pragma unroll
    for (int rp = 0; rp < 4; rp++) {
        float lo[4], hi[4];
#pragma unroll
        for (int c = 0; c < 4; c++) upk2(acc[rp * 4 + c], lo[c], hi[c]);
        int r0 = mb + ty * 8 + rp * 2;
        int col = nb + tx * 4;
        if (r0 < N_NODES)
            *(float4*)(g_h + (size_t)r0 * HF + col) = make_float4(lo[0], lo[1], lo[2], lo[3]);
        if (r0 + 1 < N_NODES)
            *(float4*)(g_h + (size_t)(r0 + 1) * HF + col) = make_float4(hi[0], hi[1], hi[2], hi[3]);

        // per-thread partial dots: rows r0 (lo) and r0+1 (hi), 4 cols each
        float s_lo = lo[0] * ws.x + lo[1] * ws.y + lo[2] * ws.z + lo[3] * ws.w;
        float s_hi = hi[0] * ws.x + hi[1] * ws.y + hi[2] * ws.z + hi[3] * ws.w;
        float d_lo = lo[0] * wd.x + lo[1] * wd.y + lo[2] * wd.z + lo[3] * wd.w;
        float d_hi = hi[0] * wd.x + hi[1] * wd.y + hi[2] * wd.z + hi[3] * wd.w;
        // reduce across the 16-lane tx group (xor stays within the half-warp)
#pragma unroll
        for (int o = 8; o; o >>= 1) {
            s_lo += __shfl_xor_sync(0xffffffffu, s_lo, o);
            s_hi += __shfl_xor_sync(0xffffffffu, s_hi, o);
            d_lo += __shfl_xor_sync(0xffffffffu, d_lo, o);
            d_hi += __shfl_xor_sync(0xffffffffu, d_hi, o);
        }
        if (tx == 0) {
            if (r0 < N_NODES) {
                g_asrc[r0 * HEADS + hd] = s_lo;
                g_adst[r0 * HEADS + hd] = d_lo;
            }
            if (r0 + 1 < N_NODES) {
                g_asrc[(r0 + 1) * HEADS + hd] = s_hi;
                g_adst[(r0 + 1) * HEADS + hd] = d_hi;
            }
        }
    }
}

// ---------------- CSR build (edge_index is int32: JAX x64 is disabled) ------
__global__ void zero_deg_kernel() {
    int i = blockIdx.x * blockDim.x + threadIdx.x;
    if (i < N_NODES) g_deg[i] = 0;
}

__global__ void hist_kernel(const int* __restrict__ ei) {
    int e = blockIdx.x * blockDim.x + threadIdx.x;
    if (e >= N_EDGES) return;
    int d = ei[N_EDGES + e];
    if ((unsigned)d < N_NODES) atomicAdd(&g_deg[d], 1);
}

__global__ __launch_bounds__(1024) void scan_kernel() {
    __shared__ int tmp[1024];
    const int tid = threadIdx.x;
    const int CH = (N_NODES + 1023) / 1024;   // 49
    int start = tid * CH;
    int end = start + CH; if (end > N_NODES) end = N_NODES;
    int s = 0;
    for (int i = start; i < end; i++) s += g_deg[i];
    tmp[tid] = s;
    __syncthreads();
    for (int off = 1; off < 1024; off <<= 1) {
        int v = tmp[tid];
        if (tid >= off) v += tmp[tid - off];
        __syncthreads();
        tmp[tid] = v;
        __syncthreads();
    }
    int run = (tid == 0) ? 0 : tmp[tid - 1];
    for (int i = start; i < end; i++) {
        g_off[i] = run;
        g_cursor[i] = run;
        run += g_deg[i];
    }
    if (tid == 0) g_off[N_NODES] = tmp[1023];
}

__global__ void scatter_kernel(const int* __restrict__ ei) {
    int e = blockIdx.x * blockDim.x + threadIdx.x;
    if (e >= N_EDGES) return;
    int s = ei[e];
    int d = ei[N_EDGES + e];
    if ((unsigned)d >= N_NODES || (unsigned)s >= N_NODES) return;
    int pos = atomicAdd(&g_cursor[d], 1);
    g_csr[pos] = s;
}

// Canonicalize each segment (odd-even transposition sort, warp per node) so
// the accumulation order — and thus the fp32 output bits — is deterministic
// even though the atomic scatter order is not.
__global__ void sortseg_kernel() {
    int gw = (blockIdx.x * blockDim.x + threadIdx.x) >> 5;
    int lane = threadIdx.x & 31;
    if (gw >= N_NODES) return;
    int lo = g_off[gw], hi = g_off[gw + 1];
    int len = hi - lo;
    if (len < 2) return;
    for (int pass = 0; pass < len; pass++) {
        int start = lo + (pass & 1);
        for (int i = start + 2 * lane; i + 1 < hi; i += 64) {
            int a = g_csr[i], b = g_csr[i + 1];
            if (a > b) { g_csr[i] = b; g_csr[i + 1] = a; }
        }
        __syncwarp();
    }
}

// ------- aggregation: warp per node, all 4 heads fused, branchless softmax --
// lane l owns floats [8l, 8l+8) of the 1KB h-row; head = l>>3.
__global__ __launch_bounds__(256) void agg_kernel(const float* __restrict__ bias,
                                                  float* __restrict__ out) {
    int n = (blockIdx.x * blockDim.x + threadIdx.x) >> 5;
    int lane = threadIdx.x & 31;
    if (n >= N_NODES) return;
    int hd = lane >> 3;

    const float4* hrow = (const float4*)(g_h + (size_t)n * HF);
    float4 aA = hrow[lane * 2];
    float4 aB = hrow[lane * 2 + 1];

    float4 adv = *(const float4*)(g_adst + n * HEADS);
    float adn = (hd == 0) ? adv.x : (hd == 1) ? adv.y : (hd == 2) ? adv.z : adv.w;
    float4 asv = *(const float4*)(g_asrc + n * HEADS);
    float e0 = ((hd == 0) ? asv.x : (hd == 1) ? asv.y : (hd == 2) ? asv.z : asv.w) + adn;
    e0 = (e0 > 0.f) ? e0 : NEG_SLOPE * e0;   // self-loop seeds the state
    float m = e0, ssum = 1.0f;

    int lo = g_off[n], hi = g_off[n + 1];
    int sj = (lo < hi) ? g_csr[lo] : 0;      // prefetched src id
    for (int j = lo; j < hi; j++) {
        int s = sj;
        if (j + 1 < hi) sj = g_csr[j + 1];
        float4 av = *(const float4*)(g_asrc + s * HEADS);      // warp broadcast
        const float4* hs = (const float4*)(g_h + (size_t)s * HF);
        float4 v0 = hs[lane * 2];
        float4 v1 = hs[lane * 2 + 1];
        float e = ((hd == 0) ? av.x : (hd == 1) ? av.y : (hd == 2) ? av.z : av.w) + adn;
        e = (e > 0.f) ? e : NEG_SLOPE * e;
        float nm = fmaxf(m, e);
        float corr = __expf(m - nm);   // == 1.0 exactly when m stays max
        float w = __expf(e - nm);
        ssum = ssum * corr + w;
        aA.x = aA.x * corr + w * v0.x;  aA.y = aA.y * corr + w * v0.y;
        aA.z = aA.z * corr + w * v0.z;  aA.w = aA.w * corr + w * v0.w;
        aB.x = aB.x * corr + w * v1.x;  aB.y = aB.y * corr + w * v1.y;
        aB.z = aB.z * corr + w * v1.z;  aB.w = aB.w * corr + w * v1.w;
        m = nm;
    }

    float inv = 1.0f / ssum;
    float4 b0 = *(const float4*)(bias + lane * 8);
    float4 b1 = *(const float4*)(bias + lane * 8 + 4);
    float4* orow = (float4*)(out + (size_t)n * HF);
    orow[lane * 2]     = make_float4(aA.x * inv + b0.x, aA.y * inv + b0.y,
                                     aA.z * inv + b0.z, aA.w * inv + b0.w);
    orow[lane * 2 + 1] = make_float4(aB.x * inv + b1.x, aB.y * inv + b1.y,
                                     aB.z * inv + b1.z, aB.w * inv + b1.w);
}

// ---------------- launch ----------------------------------------------------
extern "C" void kernel_launch(void* const* d_in, const int* in_sizes, int n_in,
                              void* d_out, int out_size) {
    const float* x     = (const float*)d_in[0];
    const int*   ei    = (const int*)d_in[1];       // int32: JAX x64 disabled
    const float* W     = (const float*)d_in[2];
    const float* att_s = (const float*)d_in[3];
    const float* att_d = (const float*)d_in[4];
    const float* bias  = (const float*)d_in[5];
    float*       out   = (float*)d_out;
    (void)in_sizes; (void)n_in; (void)out_size;

    gemm_kernel<<<dim3((N_NODES + BM - 1) / BM, HF / BN), 256>>>(x, W, att_s, att_d);
    zero_deg_kernel<<<(N_NODES + 255) / 256, 256>>>();
    hist_kernel<<<(N_EDGES + 255) / 256, 256>>>(ei);
    scan_kernel<<<1, 1024>>>();
    scatter_kernel<<<(N_EDGES + 255) / 256, 256>>>(ei);
    sortseg_kernel<<<(N_NODES * 32 + 255) / 256, 256>>>();
    agg_kernel<<<(N_NODES * 32 + 255) / 256, 256>>>(bias, out);
}

// round 7
// speedup vs baseline: 1.4323x; 1.1977x over previous
#include <cuda_runtime.h>
#include <cstdint>

#define N_NODES 50000
#define N_EDGES 800000
#define IN_F 256
#define HEADS 4
#define OUT_F 64
#define HF 256            // HEADS * OUT_F
#define NEG_SLOPE 0.2f

#define SCAN_CHUNK 512
#define NBLK ((N_NODES + SCAN_CHUNK - 1) / SCAN_CHUNK)   // 98

// ---------------- scratch (static device allocations; no cudaMalloc) --------
__device__ float g_h[(size_t)N_NODES * HF];      // 51.2 MB  projected features
__device__ float g_asrc[N_NODES * HEADS];
__device__ float g_adst[N_NODES * HEADS];
__device__ int   g_deg[N_NODES];
__device__ int   g_off[N_NODES + 1];
__device__ int   g_cursor[N_NODES];
__device__ int   g_csr[N_EDGES];                 // src ids grouped by dst
__device__ int   g_bsum[NBLK];
__device__ int   g_boff[NBLK];

// ---------------- packed f32x2 helpers (Blackwell dual-FP32 pipe) -----------
__device__ __forceinline__ unsigned long long pk2(float lo, float hi) {
    unsigned long long r;
    asm("mov.b64 %0, {%1,%2};" : "=l"(r) : "f"(lo), "f"(hi));
    return r;
}
__device__ __forceinline__ void upk2(unsigned long long v, float& lo, float& hi) {
    asm("mov.b64 {%0,%1}, %2;" : "=f"(lo), "=f"(hi) : "l"(v));
}
#define FMA2(d, a, b) asm("fma.rn.f32x2 %0, %1, %2, %0;" : "+l"(d) : "l"(a), "l"(b))

// ------- GEMM: g_h = x @ W  (fp32, f32x2 FMA) + fused a_src/a_dst epilogue --
#define BM 128
#define BN 64
#define BK 16
#define APAD 132   // pad to reduce STS bank conflicts; keeps 16B alignment

__global__ __launch_bounds__(256) void gemm_kernel(const float* __restrict__ A,
                                                   const float* __restrict__ B,
                                                   const float* __restrict__ att_s,
                                                   const float* __restrict__ att_d) {
    __shared__ __align__(16) float  As[BK][APAD];   // stored [k][m]
    __shared__ float4 Bs[BK][BN / 4];               // stored [k][n/4]

    const int tid = threadIdx.x;
    const int tx = tid & 15;       // 16 col groups * 4 cols
    const int ty = tid >> 4;       // 16 row groups * 8 rows
    const int mb = blockIdx.x * BM;
    const int hd = blockIdx.y;     // head index; nb = hd*64
    const int nb = hd * BN;

    unsigned long long acc[16];    // 4 row-pairs x 4 cols, each (row2r, row2r+1)
#pragma unroll
    for (int i = 0; i < 16; i++) acc[i] = 0ULL;

    for (int kt = 0; kt < IN_F / BK; kt++) {
#pragma unroll
        for (int i = 0; i < 2; i++) {
            int j = tid + i * 256;
            int r = j >> 2;
            int kc = (j & 3) << 2;
            int grow = mb + r;
            float4 v = make_float4(0.f, 0.f, 0.f, 0.f);
            if (grow < N_NODES)
                v = *(const float4*)(A + (size_t)grow * IN_F + kt * BK + kc);
            As[kc][r] = v.x; As[kc + 1][r] = v.y;
            As[kc + 2][r] = v.z; As[kc + 3][r] = v.w;
        }
        {
            int r = tid >> 4, c4 = tid & 15;
            Bs[r][c4] = *(const float4*)(B + (size_t)(kt * BK + r) * HF + nb + c4 * 4);
        }
        __syncthreads();

#pragma unroll
        for (int k = 0; k < BK; k++) {
            float4 a0 = *(const float4*)&As[k][ty * 8];       // broadcast reads
            float4 a1 = *(const float4*)&As[k][ty * 8 + 4];
            float4 b  = Bs[k][tx];
            unsigned long long A01 = pk2(a0.x, a0.y);
            unsigned long long A23 = pk2(a0.z, a0.w);
            unsigned long long A45 = pk2(a1.x, a1.y);
            unsigned long long A67 = pk2(a1.z, a1.w);
            float bc[4] = {b.x, b.y, b.z, b.w};
#pragma unroll
            for (int c = 0; c < 4; c++) {
                unsigned long long bb = pk2(bc[c], bc[c]);
                FMA2(acc[0  + c], A01, bb);
                FMA2(acc[4  + c], A23, bb);
                FMA2(acc[8  + c], A45, bb);
                FMA2(acc[12 + c], A67, bb);
            }
        }
        __syncthreads();
    }

    const float4 ws = *(const float4*)(att_s + hd * OUT_F + tx * 4);
    const float4 wd = *(const float4*)(att_d + hd * OUT_F + tx * 4);

#pragma unroll
    for (int rp = 0; rp < 4; rp++) {
        float lo[4], hi[4];
#pragma unroll
        for (int c = 0; c < 4; c++) upk2(acc[rp * 4 + c], lo[c], hi[c]);
        int r0 = mb + ty * 8 + rp * 2;
        int col = nb + tx * 4;
        if (r0 < N_NODES)
            *(float4*)(g_h + (size_t)r0 * HF + col) = make_float4(lo[0], lo[1], lo[2], lo[3]);
        if (r0 + 1 < N_NODES)
            *(float4*)(g_h + (size_t)(r0 + 1) * HF + col) = make_float4(hi[0], hi[1], hi[2], hi[3]);

        float s_lo = lo[0] * ws.x + lo[1] * ws.y + lo[2] * ws.z + lo[3] * ws.w;
        float s_hi = hi[0] * ws.x + hi[1] * ws.y + hi[2] * ws.z + hi[3] * ws.w;
        float d_lo = lo[0] * wd.x + lo[1] * wd.y + lo[2] * wd.z + lo[3] * wd.w;
        float d_hi = hi[0] * wd.x + hi[1] * wd.y + hi[2] * wd.z + hi[3] * wd.w;
#pragma unroll
        for (int o = 8; o; o >>= 1) {
            s_lo += __shfl_xor_sync(0xffffffffu, s_lo, o);
            s_hi += __shfl_xor_sync(0xffffffffu, s_hi, o);
            d_lo += __shfl_xor_sync(0xffffffffu, d_lo, o);
            d_hi += __shfl_xor_sync(0xffffffffu, d_hi, o);
        }
        if (tx == 0) {
            if (r0 < N_NODES) {
                g_asrc[r0 * HEADS + hd] = s_lo;
                g_adst[r0 * HEADS + hd] = d_lo;
            }
            if (r0 + 1 < N_NODES) {
                g_asrc[(r0 + 1) * HEADS + hd] = s_hi;
                g_adst[(r0 + 1) * HEADS + hd] = d_hi;
            }
        }
    }
}

// ---------------- CSR build (edge_index is int32: JAX x64 is disabled) ------
__global__ void zero_deg_kernel() {
    int i = blockIdx.x * blockDim.x + threadIdx.x;
    if (i < N_NODES) g_deg[i] = 0;
}

__global__ void hist_kernel(const int* __restrict__ ei) {
    int e = blockIdx.x * blockDim.x + threadIdx.x;
    if (e >= N_EDGES) return;
    int d = ei[N_EDGES + e];
    if ((unsigned)d < N_NODES) atomicAdd(&g_deg[d], 1);
}

// --- stage 1: per-block degree sums (98 blocks x 512 threads) ---------------
__global__ __launch_bounds__(SCAN_CHUNK) void blockred_kernel() {
    __shared__ int sh[SCAN_CHUNK];
    int i = blockIdx.x * SCAN_CHUNK + threadIdx.x;
    int v = (i < N_NODES) ? g_deg[i] : 0;
    sh[threadIdx.x] = v;
    __syncthreads();
#pragma unroll
    for (int off = SCAN_CHUNK / 2; off >= 32; off >>= 1) {
        if (threadIdx.x < off) sh[threadIdx.x] += sh[threadIdx.x + off];
        __syncthreads();
    }
    if (threadIdx.x < 32) {
        int s = sh[threadIdx.x];
#pragma unroll
        for (int o = 16; o; o >>= 1) s += __shfl_xor_sync(0xffffffffu, s, o);
        if (threadIdx.x == 0) g_bsum[blockIdx.x] = s;
    }
}

// --- stage 2: exclusive scan of the 98 block sums (one tiny block) ----------
__global__ __launch_bounds__(128) void scanblk_kernel() {
    __shared__ int sh[128];
    int tid = threadIdx.x;
    int v = (tid < NBLK) ? g_bsum[tid] : 0;
    sh[tid] = v;
    __syncthreads();
#pragma unroll
    for (int off = 1; off < 128; off <<= 1) {
        int t = sh[tid];
        if (tid >= off) t += sh[tid - off];
        __syncthreads();
        sh[tid] = t;
        __syncthreads();
    }
    if (tid < NBLK) g_boff[tid] = sh[tid] - v;     // exclusive
    if (tid == 0) g_off[N_NODES] = sh[NBLK - 1];   // total
}

// --- stage 3: per-block 512-wide scan + offset -> g_off / g_cursor ----------
__global__ __launch_bounds__(SCAN_CHUNK) void offsets_kernel() {
    __shared__ int sh[SCAN_CHUNK];
    int tid = threadIdx.x;
    int i = blockIdx.x * SCAN_CHUNK + tid;
    int v = (i < N_NODES) ? g_deg[i] : 0;
    sh[tid] = v;
    __syncthreads();
#pragma unroll
    for (int off = 1; off < SCAN_CHUNK; off <<= 1) {
        int t = sh[tid];
        if (tid >= off) t += sh[tid - off];
        __syncthreads();
        sh[tid] = t;
        __syncthreads();
    }
    if (i < N_NODES) {
        int excl = g_boff[blockIdx.x] + sh[tid] - v;
        g_off[i] = excl;
        g_cursor[i] = excl;
    }
}

__global__ void scatter_kernel(const int* __restrict__ ei) {
    int e = blockIdx.x * blockDim.x + threadIdx.x;
    if (e >= N_EDGES) return;
    int s = ei[e];
    int d = ei[N_EDGES + e];
    if ((unsigned)d >= N_NODES || (unsigned)s >= N_NODES) return;
    int pos = atomicAdd(&g_cursor[d], 1);
    g_csr[pos] = s;
}

// Canonicalize each segment (odd-even transposition sort, warp per node) so
// the accumulation order — and thus the fp32 output bits — is deterministic.
__global__ void sortseg_kernel() {
    int gw = (blockIdx.x * blockDim.x + threadIdx.x) >> 5;
    int lane = threadIdx.x & 31;
    if (gw >= N_NODES) return;
    int lo = g_off[gw], hi = g_off[gw + 1];
    int len = hi - lo;
    if (len < 2) return;
    for (int pass = 0; pass < len; pass++) {
        int start = lo + (pass & 1);
        for (int i = start + 2 * lane; i + 1 < hi; i += 64) {
            int a = g_csr[i], b = g_csr[i + 1];
            if (a > b) { g_csr[i] = b; g_csr[i + 1] = a; }
        }
        __syncwarp();
    }
}

// ------- aggregation: warp per node, 4 heads fused, 2-deep SW pipeline ------
// lane l owns floats [8l, 8l+8) of the 1KB h-row; head = l>>3.
// Arithmetic order is strictly edge-by-edge (sorted), so results are
// bit-deterministic; only the LOADS are pipelined one edge ahead.
__global__ __launch_bounds__(256) void agg_kernel(const float* __restrict__ bias,
                                                  float* __restrict__ out) {
    int n = (blockIdx.x * blockDim.x + threadIdx.x) >> 5;
    int lane = threadIdx.x & 31;
    if (n >= N_NODES) return;
    int hd = lane >> 3;

    const float4* hrow = (const float4*)(g_h + (size_t)n * HF);
    float4 aA = hrow[lane * 2];
    float4 aB = hrow[lane * 2 + 1];

    float4 adv = *(const float4*)(g_adst + n * HEADS);
    float adn = (hd == 0) ? adv.x : (hd == 1) ? adv.y : (hd == 2) ? adv.z : adv.w;
    float4 asv = *(const float4*)(g_asrc + n * HEADS);
    float e0 = ((hd == 0) ? asv.x : (hd == 1) ? asv.y : (hd == 2) ? asv.z : asv.w) + adn;
    e0 = (e0 > 0.f) ? e0 : NEG_SLOPE * e0;   // self-loop seeds the state
    float m = e0, ssum = 1.0f;

    int lo = g_off[n], hi = g_off[n + 1];

    float4 av, v0, v1;               // current edge operands
    if (lo < hi) {                   // prime the pipeline with edge lo
        int s0 = g_csr[lo];
        av = *(const float4*)(g_asrc + s0 * HEADS);
        const float4* hs = (const float4*)(g_h + (size_t)s0 * HF);
        v0 = hs[lane * 2];
        v1 = hs[lane * 2 + 1];
    }
    for (int j = lo; j < hi; j++) {
        float4 cav = av, cv0 = v0, cv1 = v1;
        if (j + 1 < hi) {            // issue next edge's loads before compute
            int s1 = g_csr[j + 1];
            av = *(const float4*)(g_asrc + s1 * HEADS);
            const float4* hs = (const float4*)(g_h + (size_t)s1 * HF);
            v0 = hs[lane * 2];
            v1 = hs[lane * 2 + 1];
        }
        float e = ((hd == 0) ? cav.x : (hd == 1) ? cav.y : (hd == 2) ? cav.z : cav.w) + adn;
        e = (e > 0.f) ? e : NEG_SLOPE * e;
        float nm = fmaxf(m, e);
        float corr = __expf(m - nm);   // == 1.0 exactly when m stays max
        float w = __expf(e - nm);
        ssum = ssum * corr + w;
        aA.x = aA.x * corr + w * cv0.x;  aA.y = aA.y * corr + w * cv0.y;
        aA.z = aA.z * corr + w * cv0.z;  aA.w = aA.w * corr + w * cv0.w;
        aB.x = aB.x * corr + w * cv1.x;  aB.y = aB.y * corr + w * cv1.y;
        aB.z = aB.z * corr + w * cv1.z;  aB.w = aB.w * corr + w * cv1.w;
        m = nm;
    }

    float inv = 1.0f / ssum;
    float4 b0 = *(const float4*)(bias + lane * 8);
    float4 b1 = *(const float4*)(bias + lane * 8 + 4);
    float4* orow = (float4*)(out + (size_t)n * HF);
    orow[lane * 2]     = make_float4(aA.x * inv + b0.x, aA.y * inv + b0.y,
                                     aA.z * inv + b0.z, aA.w * inv + b0.w);
    orow[lane * 2 + 1] = make_float4(aB.x * inv + b1.x, aB.y * inv + b1.y,
                                     aB.z * inv + b1.z, aB.w * inv + b1.w);
}

// ---------------- launch ----------------------------------------------------
extern "C" void kernel_launch(void* const* d_in, const int* in_sizes, int n_in,
                              void* d_out, int out_size) {
    const float* x     = (const float*)d_in[0];
    const int*   ei    = (const int*)d_in[1];       // int32: JAX x64 disabled
    const float* W     = (const float*)d_in[2];
    const float* att_s = (const float*)d_in[3];
    const float* att_d = (const float*)d_in[4];
    const float* bias  = (const float*)d_in[5];
    float*       out   = (float*)d_out;
    (void)in_sizes; (void)n_in; (void)out_size;

    gemm_kernel<<<dim3((N_NODES + BM - 1) / BM, HF / BN), 256>>>(x, W, att_s, att_d);
    zero_deg_kernel<<<(N_NODES + 255) / 256, 256>>>();
    hist_kernel<<<(N_EDGES + 255) / 256, 256>>>(ei);
    blockred_kernel<<<NBLK, SCAN_CHUNK>>>();
    scanblk_kernel<<<1, 128>>>();
    offsets_kernel<<<NBLK, SCAN_CHUNK>>>();
    scatter_kernel<<<(N_EDGES + 255) / 256, 256>>>(ei);
    sortseg_kernel<<<(N_NODES * 32 + 255) / 256, 256>>>();
    agg_kernel<<<(N_NODES * 32 + 255) / 256, 256>>>(bias, out);
}

// round 9
// speedup vs baseline: 1.4580x; 1.0179x over previous
#include <cuda_runtime.h>
#include <cuda_bf16.h>
#include <cstdint>

#define N_NODES 50000
#define N_EDGES 800000
#define IN_F 256
#define HEADS 4
#define OUT_F 64
#define HF 256            // HEADS * OUT_F
#define NEG_SLOPE 0.2f

#define SCAN_CHUNK 512
#define NBLK ((N_NODES + SCAN_CHUNK - 1) / SCAN_CHUNK)   // 98

// ---------------- scratch (static device allocations; no cudaMalloc) --------
__device__ float g_h[(size_t)N_NODES * HF];      // 51.2 MB  projected features
__device__ __nv_bfloat16 g_xhi[(size_t)N_NODES * IN_F];   // 25.6 MB
__device__ __nv_bfloat16 g_xlo[(size_t)N_NODES * IN_F];   // 25.6 MB
__device__ __nv_bfloat16 g_Whi[IN_F * HF];
__device__ __nv_bfloat16 g_Wlo[IN_F * HF];
__device__ float g_asrc[N_NODES * HEADS];
__device__ float g_adst[N_NODES * HEADS];
__device__ int   g_deg[N_NODES];
__device__ int   g_off[N_NODES + 1];
__device__ int   g_cursor[N_NODES];
__device__ int   g_csr[N_EDGES];                 // src ids grouped by dst
__device__ int   g_bsum[NBLK];
__device__ int   g_boff[NBLK];

// ---------------- split kernels: v -> bf16 hi + bf16 residual ---------------
__global__ void wsplit_kernel(const float* __restrict__ W) {
    int i = blockIdx.x * blockDim.x + threadIdx.x;
    if (i >= IN_F * HF) return;
    float w = W[i];
    __nv_bfloat16 hi = __float2bfloat16(w);
    __nv_bfloat16 lo = __float2bfloat16(w - __bfloat162float(hi));
    g_Whi[i] = hi;
    g_Wlo[i] = lo;
}

__global__ __launch_bounds__(256) void xsplit_kernel(const float* __restrict__ x) {
    // warp per node; lane owns 8 consecutive floats
    int n = (blockIdx.x * blockDim.x + threadIdx.x) >> 5;
    int lane = threadIdx.x & 31;
    if (n >= N_NODES) return;
    const float4* xr = (const float4*)(x + (size_t)n * IN_F) + lane * 2;
    float4 xa = xr[0], xb = xr[1];
    float xs[8] = {xa.x, xa.y, xa.z, xa.w, xb.x, xb.y, xb.z, xb.w};
    union { __nv_bfloat16 b[8]; uint4 u; } H, L;
#pragma unroll
    for (int i = 0; i < 8; i++) {
        H.b[i] = __float2bfloat16(xs[i]);
        L.b[i] = __float2bfloat16(xs[i] - __bfloat162float(H.b[i]));
    }
    *(uint4*)(g_xhi + (size_t)n * IN_F + lane * 8) = H.u;
    *(uint4*)(g_xlo + (size_t)n * IN_F + lane * 8) = L.u;
}

// ---------------- GEMM: g_h = x @ W via 3 bf16 tensor-core passes -----------
// hi*hi + hi*lo + lo*hi  (lo*lo dropped, ~2^-16 relative)
#define ASTRIDE 40   // bf16 elements per A smem row (80B, conflict-free ldmatrix)
#define BSTRIDE 72   // bf16 elements per B smem row (144B)

__device__ __forceinline__ void ldsm4(uint32_t* r, const __nv_bfloat16* p) {
    unsigned a = (unsigned)__cvta_generic_to_shared(p);
    asm volatile("ldmatrix.sync.aligned.m8n8.x4.shared.b16 {%0,%1,%2,%3}, [%4];"
                 : "=r"(r[0]), "=r"(r[1]), "=r"(r[2]), "=r"(r[3]) : "r"(a));
}
__device__ __forceinline__ void ldsm4t(uint32_t* r, const __nv_bfloat16* p) {
    unsigned a = (unsigned)__cvta_generic_to_shared(p);
    asm volatile("ldmatrix.sync.aligned.m8n8.x4.trans.shared.b16 {%0,%1,%2,%3}, [%4];"
                 : "=r"(r[0]), "=r"(r[1]), "=r"(r[2]), "=r"(r[3]) : "r"(a));
}
__device__ __forceinline__ void mma16816(float* c, const uint32_t* a, uint32_t b0, uint32_t b1) {
    asm volatile("mma.sync.aligned.m16n8k16.row.col.f32.bf16.bf16.f32 "
                 "{%0,%1,%2,%3}, {%4,%5,%6,%7}, {%8,%9}, {%0,%1,%2,%3};"
                 : "+f"(c[0]), "+f"(c[1]), "+f"(c[2]), "+f"(c[3])
                 : "r"(a[0]), "r"(a[1]), "r"(a[2]), "r"(a[3]), "r"(b0), "r"(b1));
}

__global__ __launch_bounds__(256) void gemm_bf16_kernel() {
    __shared__ __align__(16) __nv_bfloat16 sA[128 * ASTRIDE];  // 10240 B
    __shared__ __align__(16) __nv_bfloat16 sB[32 * BSTRIDE];   //  4608 B

    const int tid = threadIdx.x;
    const int lane = tid & 31;
    const int wid = tid >> 5;
    const int wm = wid & 3;        // 4 M-warps of 32 rows
    const int wn = wid >> 2;       // 2 N-warps of 32 cols
    const int mb = blockIdx.x * 128;
    const int nb = blockIdx.y * 64;
    const int lrow = lane & 15;
    const int lcol8 = (lane >> 4) << 3;   // 0 or 8 (bf16 elements)

    float acc[2][4][4];
#pragma unroll
    for (int i = 0; i < 2; i++)
#pragma unroll
        for (int j = 0; j < 4; j++)
#pragma unroll
            for (int k = 0; k < 4; k++) acc[i][j][k] = 0.f;

#pragma unroll 1
    for (int seg = 0; seg < 3; seg++) {
        const __nv_bfloat16* Ag = (seg == 2) ? g_xlo : g_xhi;
        const __nv_bfloat16* Bg = (seg == 1) ? g_Wlo : g_Whi;
#pragma unroll 1
        for (int kt = 0; kt < IN_F; kt += 32) {
            // A tile: 128 rows x 32 bf16 = 512 x 16B chunks, 2 per thread
#pragma unroll
            for (int i = 0; i < 2; i++) {
                int c = tid + i * 256;
                int r = c >> 2, c16 = c & 3;
                int grow = mb + r;
                uint4 v = make_uint4(0, 0, 0, 0);
                if (grow < N_NODES)
                    v = *(const uint4*)(Ag + (size_t)grow * IN_F + kt + c16 * 8);
                *(uint4*)(sA + r * ASTRIDE + c16 * 8) = v;
            }
            // B tile: 32 rows x 64 bf16 = 256 x 16B chunks, 1 per thread
            {
                int r = tid >> 3, c16 = tid & 7;
                uint4 v = *(const uint4*)(Bg + (size_t)(kt + r) * HF + nb + c16 * 8);
                *(uint4*)(sB + r * BSTRIDE + c16 * 8) = v;
            }
            __syncthreads();

            uint32_t a[2][2][4], b[2][2][4];
#pragma unroll
            for (int mt = 0; mt < 2; mt++)
#pragma unroll
                for (int kc = 0; kc < 2; kc++)
                    ldsm4(a[mt][kc],
                          sA + (wm * 32 + mt * 16 + lrow) * ASTRIDE + kc * 16 + lcol8);
#pragma unroll
            for (int kc = 0; kc < 2; kc++)
#pragma unroll
                for (int nt2 = 0; nt2 < 2; nt2++)
                    ldsm4t(b[kc][nt2],
                           sB + (kc * 16 + lrow) * BSTRIDE + wn * 32 + nt2 * 16 + lcol8);
#pragma unroll
            for (int mt = 0; mt < 2; mt++)
#pragma unroll
                for (int nt = 0; nt < 4; nt++)
#pragma unroll
                    for (int kc = 0; kc < 2; kc++) {
                        uint32_t* bb = &b[kc][nt >> 1][(nt & 1) * 2];
                        mma16816(acc[mt][nt], a[mt][kc], bb[0], bb[1]);
                    }
            __syncthreads();
        }
    }

    // epilogue: c0,c1 -> row (lane>>2), cols col..col+1; c2,c3 -> row+8
#pragma unroll
    for (int mt = 0; mt < 2; mt++) {
        int row0 = mb + wm * 32 + mt * 16 + (lane >> 2);
#pragma unroll
        for (int nt = 0; nt < 4; nt++) {
            int col = nb + wn * 32 + nt * 8 + (lane & 3) * 2;
            if (row0 < N_NODES)
                *(float2*)(g_h + (size_t)row0 * HF + col) =
                    make_float2(acc[mt][nt][0], acc[mt][nt][1]);
            if (row0 + 8 < N_NODES)
                *(float2*)(g_h + (size_t)(row0 + 8) * HF + col) =
                    make_float2(acc[mt][nt][2], acc[mt][nt][3]);
        }
    }
}

// ---------------- per-node attention halves: a_src, a_dst (proven in R3) ----
__global__ void att_kernel(const float* __restrict__ att_s,
                           const float* __restrict__ att_d) {
    int gw = (blockIdx.x * blockDim.x + threadIdx.x) >> 5;
    int lane = threadIdx.x & 31;
    if (gw >= N_NODES) return;
    const float* hr = g_h + (size_t)gw * HF;
#pragma unroll
    for (int hd = 0; hd < HEADS; hd++) {
        float v0 = hr[hd * 64 + lane];
        float v1 = hr[hd * 64 + 32 + lane];
        float s = v0 * att_s[hd * 64 + lane] + v1 * att_s[hd * 64 + 32 + lane];
        float d = v0 * att_d[hd * 64 + lane] + v1 * att_d[hd * 64 + 32 + lane];
#pragma unroll
        for (int o = 16; o; o >>= 1) {
            s += __shfl_xor_sync(0xffffffffu, s, o);
            d += __shfl_xor_sync(0xffffffffu, d, o);
        }
        if (lane == 0) {
            g_asrc[gw * HEADS + hd] = s;
            g_adst[gw * HEADS + hd] = d;
        }
    }
}

// ---------------- CSR build (edge_index is int32: JAX x64 is disabled) ------
__global__ void zero_deg_kernel() {
    int i = blockIdx.x * blockDim.x + threadIdx.x;
    if (i < N_NODES) g_deg[i] = 0;
}

__global__ void hist_kernel(const int* __restrict__ ei) {
    int e = blockIdx.x * blockDim.x + threadIdx.x;
    if (e >= N_EDGES) return;
    int d = ei[N_EDGES + e];
    if ((unsigned)d < N_NODES) atomicAdd(&g_deg[d], 1);
}

__global__ __launch_bounds__(SCAN_CHUNK) void blockred_kernel() {
    __shared__ int sh[SCAN_CHUNK];
    int i = blockIdx.x * SCAN_CHUNK + threadIdx.x;
    int v = (i < N_NODES) ? g_deg[i] : 0;
    sh[threadIdx.x] = v;
    __syncthreads();
#pragma unroll
    for (int off = SCAN_CHUNK / 2; off >= 32; off >>= 1) {
        if (threadIdx.x < off) sh[threadIdx.x] += sh[threadIdx.x + off];
        __syncthreads();
    }
    if (threadIdx.x < 32) {
        int s = sh[threadIdx.x];
#pragma unroll
        for (int o = 16; o; o >>= 1) s += __shfl_xor_sync(0xffffffffu, s, o);
        if (threadIdx.x == 0) g_bsum[blockIdx.x] = s;
    }
}

__global__ __launch_bounds__(128) void scanblk_kernel() {
    __shared__ int sh[128];
    int tid = threadIdx.x;
    int v = (tid < NBLK) ? g_bsum[tid] : 0;
    sh[tid] = v;
    __syncthreads();
#pragma unroll
    for (int off = 1; off < 128; off <<= 1) {
        int t = sh[tid];
        if (tid >= off) t += sh[tid - off];
        __syncthreads();
        sh[tid] = t;
        __syncthreads();
    }
    if (tid < NBLK) g_boff[tid] = sh[tid] - v;     // exclusive
    if (tid == 0) g_off[N_NODES] = sh[NBLK - 1];   // total
}

__global__ __launch_bounds__(SCAN_CHUNK) void offsets_kernel() {
    __shared__ int sh[SCAN_CHUNK];
    int tid = threadIdx.x;
    int i = blockIdx.x * SCAN_CHUNK + tid;
    int v = (i < N_NODES) ? g_deg[i] : 0;
    sh[tid] = v;
    __syncthreads();
#pragma unroll
    for (int off = 1; off < SCAN_CHUNK; off <<= 1) {
        int t = sh[tid];
        if (tid >= off) t += sh[tid - off];
        __syncthreads();
        sh[tid] = t;
        __syncthreads();
    }
    if (i < N_NODES) {
        int excl = g_boff[blockIdx.x] + sh[tid] - v;
        g_off[i] = excl;
        g_cursor[i] = excl;
    }
}

__global__ void scatter_kernel(const int* __restrict__ ei) {
    int e = blockIdx.x * blockDim.x + threadIdx.x;
    if (e >= N_EDGES) return;
    int s = ei[e];
    int d = ei[N_EDGES + e];
    if ((unsigned)d >= N_NODES || (unsigned)s >= N_NODES) return;
    int pos = atomicAdd(&g_cursor[d], 1);
    g_csr[pos] = s;
}

// Canonicalize each segment so fp32 accumulation order is deterministic.
__global__ void sortseg_kernel() {
    int gw = (blockIdx.x * blockDim.x + threadIdx.x) >> 5;
    int lane = threadIdx.x & 31;
    if (gw >= N_NODES) return;
    int lo = g_off[gw], hi = g_off[gw + 1];
    int len = hi - lo;
    if (len < 2) return;
    for (int pass = 0; pass < len; pass++) {
        int start = lo + (pass & 1);
        for (int i = start + 2 * lane; i + 1 < hi; i += 64) {
            int a = g_csr[i], b = g_csr[i + 1];
            if (a > b) { g_csr[i] = b; g_csr[i + 1] = a; }
        }
        __syncwarp();
    }
}

// ------- aggregation: warp per node, 4 heads fused, 2-deep SW pipeline ------
__global__ __launch_bounds__(256) void agg_kernel(const float* __restrict__ bias,
                                                  float* __restrict__ out) {
    int n = (blockIdx.x * blockDim.x + threadIdx.x) >> 5;
    int lane = threadIdx.x & 31;
    if (n >= N_NODES) return;
    int hd = lane >> 3;

    const float4* hrow = (const float4*)(g_h + (size_t)n * HF);
    float4 aA = hrow[lane * 2];
    float4 aB = hrow[lane * 2 + 1];

    float4 adv = *(const float4*)(g_adst + n * HEADS);
    float adn = (hd == 0) ? adv.x : (hd == 1) ? adv.y : (hd == 2) ? adv.z : adv.w;
    float4 asv = *(const float4*)(g_asrc + n * HEADS);
    float e0 = ((hd == 0) ? asv.x : (hd == 1) ? asv.y : (hd == 2) ? asv.z : asv.w) + adn;
    e0 = (e0 > 0.f) ? e0 : NEG_SLOPE * e0;   // self-loop seeds the state
    float m = e0, ssum = 1.0f;

    int lo = g_off[n], hi = g_off[n + 1];

    float4 av, v0, v1;
    if (lo < hi) {
        int s0 = g_csr[lo];
        av = *(const float4*)(g_asrc + s0 * HEADS);
        const float4* hs = (const float4*)(g_h + (size_t)s0 * HF);
        v0 = hs[lane * 2];
        v1 = hs[lane * 2 + 1];
    }
    for (int j = lo; j < hi; j++) {
        float4 cav = av, cv0 = v0, cv1 = v1;
        if (j + 1 < hi) {
            int s1 = g_csr[j + 1];
            av = *(const float4*)(g_asrc + s1 * HEADS);
            const float4* hs = (const float4*)(g_h + (size_t)s1 * HF);
            v0 = hs[lane * 2];
            v1 = hs[lane * 2 + 1];
        }
        float e = ((hd == 0) ? cav.x : (hd == 1) ? cav.y : (hd == 2) ? cav.z : cav.w) + adn;
        e = (e > 0.f) ? e : NEG_SLOPE * e;
        float nm = fmaxf(m, e);
        float corr = __expf(m - nm);
        float w = __expf(e - nm);
        ssum = ssum * corr + w;
        aA.x = aA.x * corr + w * cv0.x;  aA.y = aA.y * corr + w * cv0.y;
        aA.z = aA.z * corr + w * cv0.z;  aA.w = aA.w * corr + w * cv0.w;
        aB.x = aB.x * corr + w * cv1.x;  aB.y = aB.y * corr + w * cv1.y;
        aB.z = aB.z * corr + w * cv1.z;  aB.w = aB.w * corr + w * cv1.w;
        m = nm;
    }

    float inv = 1.0f / ssum;
    float4 b0 = *(const float4*)(bias + lane * 8);
    float4 b1 = *(const float4*)(bias + lane * 8 + 4);
    float4* orow = (float4*)(out + (size_t)n * HF);
    orow[lane * 2]     = make_float4(aA.x * inv + b0.x, aA.y * inv + b0.y,
                                     aA.z * inv + b0.z, aA.w * inv + b0.w);
    orow[lane * 2 + 1] = make_float4(aB.x * inv + b1.x, aB.y * inv + b1.y,
                                     aB.z * inv + b1.z, aB.w * inv + b1.w);
}

// ---------------- launch ----------------------------------------------------
extern "C" void kernel_launch(void* const* d_in, const int* in_sizes, int n_in,
                              void* d_out, int out_size) {
    const float* x     = (const float*)d_in[0];
    const int*   ei    = (const int*)d_in[1];       // int32: JAX x64 disabled
    const float* W     = (const float*)d_in[2];
    const float* att_s = (const float*)d_in[3];
    const float* att_d = (const float*)d_in[4];
    const float* bias  = (const float*)d_in[5];
    float*       out   = (float*)d_out;
    (void)in_sizes; (void)n_in; (void)out_size;

    wsplit_kernel<<<(IN_F * HF + 255) / 256, 256>>>(W);
    xsplit_kernel<<<(N_NODES * 32 + 255) / 256, 256>>>(x);
    gemm_bf16_kernel<<<dim3((N_NODES + 127) / 128, HF / 64), 256>>>();
    att_kernel<<<(N_NODES * 32 + 255) / 256, 256>>>(att_s, att_d);
    zero_deg_kernel<<<(N_NODES + 255) / 256, 256>>>();
    hist_kernel<<<(N_EDGES + 255) / 256, 256>>>(ei);
    blockred_kernel<<<NBLK, SCAN_CHUNK>>>();
    scanblk_kernel<<<1, 128>>>();
    offsets_kernel<<<NBLK, SCAN_CHUNK>>>();
    scatter_kernel<<<(N_EDGES + 255) / 256, 256>>>(ei);
    sortseg_kernel<<<(N_NODES * 32 + 255) / 256, 256>>>();
    agg_kernel<<<(N_NODES * 32 + 255) / 256, 256>>>(bias, out);
}

// round 10
// speedup vs baseline: 1.4667x; 1.0060x over previous
#include <cuda_runtime.h>
#include <cuda_bf16.h>
#include <cstdint>

#define N_NODES 50000
#define N_EDGES 800000
#define IN_F 256
#define HEADS 4
#define OUT_F 64
#define HF 256            // HEADS * OUT_F
#define NEG_SLOPE 0.2f

#define SCAN_CHUNK 512
#define NBLK ((N_NODES + SCAN_CHUNK - 1) / SCAN_CHUNK)   // 98

// ---------------- scratch (static device allocations; no cudaMalloc) --------
__device__ float g_h[(size_t)N_NODES * HF];      // 51.2 MB  projected features
__device__ __nv_bfloat16 g_xhi[(size_t)N_NODES * IN_F];   // 25.6 MB
__device__ __nv_bfloat16 g_xlo[(size_t)N_NODES * IN_F];   // 25.6 MB
__device__ __nv_bfloat16 g_Whi[IN_F * HF];
__device__ __nv_bfloat16 g_Wlo[IN_F * HF];
__device__ float g_asrc[N_NODES * HEADS];
__device__ float g_adst[N_NODES * HEADS];
__device__ int   g_deg[N_NODES];
__device__ int   g_off[N_NODES + 1];
__device__ int   g_cursor[N_NODES];
__device__ int   g_csr[N_EDGES];                 // src ids grouped by dst
__device__ int   g_bsum[NBLK];
__device__ int   g_boff[NBLK];

// ---------------- split kernels: v -> bf16 hi + bf16 residual ---------------
__global__ void wsplit_kernel(const float* __restrict__ W) {
    int i = blockIdx.x * blockDim.x + threadIdx.x;
    if (i >= IN_F * HF) return;
    float w = W[i];
    __nv_bfloat16 hi = __float2bfloat16(w);
    __nv_bfloat16 lo = __float2bfloat16(w - __bfloat162float(hi));
    g_Whi[i] = hi;
    g_Wlo[i] = lo;
}

__global__ __launch_bounds__(256) void xsplit_kernel(const float* __restrict__ x) {
    // warp per node; lane owns 8 consecutive floats
    int n = (blockIdx.x * blockDim.x + threadIdx.x) >> 5;
    int lane = threadIdx.x & 31;
    if (n >= N_NODES) return;
    const float4* xr = (const float4*)(x + (size_t)n * IN_F) + lane * 2;
    float4 xa = xr[0], xb = xr[1];
    float xs[8] = {xa.x, xa.y, xa.z, xa.w, xb.x, xb.y, xb.z, xb.w};
    union { __nv_bfloat16 b[8]; uint4 u; } H, L;
#pragma unroll
    for (int i = 0; i < 8; i++) {
        H.b[i] = __float2bfloat16(xs[i]);
        L.b[i] = __float2bfloat16(xs[i] - __bfloat162float(H.b[i]));
    }
    *(uint4*)(g_xhi + (size_t)n * IN_F + lane * 8) = H.u;
    *(uint4*)(g_xlo + (size_t)n * IN_F + lane * 8) = L.u;
}

// ---------------- GEMM: g_h = x @ W via 3 bf16 tensor-core passes -----------
// hi*hi + hi*lo + lo*hi  (lo*lo dropped, ~2^-16 relative)
#define ASTRIDE 40   // bf16 elements per A smem row (80B, conflict-free ldmatrix)
#define BSTRIDE 72   // bf16 elements per B smem row (144B)

__device__ __forceinline__ void ldsm4(uint32_t* r, const __nv_bfloat16* p) {
    unsigned a = (unsigned)__cvta_generic_to_shared(p);
    asm volatile("ldmatrix.sync.aligned.m8n8.x4.shared.b16 {%0,%1,%2,%3}, [%4];"
                 : "=r"(r[0]), "=r"(r[1]), "=r"(r[2]), "=r"(r[3]) : "r"(a));
}
__device__ __forceinline__ void ldsm4t(uint32_t* r, const __nv_bfloat16* p) {
    unsigned a = (unsigned)__cvta_generic_to_shared(p);
    asm volatile("ldmatrix.sync.aligned.m8n8.x4.trans.shared.b16 {%0,%1,%2,%3}, [%4];"
                 : "=r"(r[0]), "=r"(r[1]), "=r"(r[2]), "=r"(r[3]) : "r"(a));
}
__device__ __forceinline__ void mma16816(float* c, const uint32_t* a, uint32_t b0, uint32_t b1) {
    asm volatile("mma.sync.aligned.m16n8k16.row.col.f32.bf16.bf16.f32 "
                 "{%0,%1,%2,%3}, {%4,%5,%6,%7}, {%8,%9}, {%0,%1,%2,%3};"
                 : "+f"(c[0]), "+f"(c[1]), "+f"(c[2]), "+f"(c[3])
                 : "r"(a[0]), "r"(a[1]), "r"(a[2]), "r"(a[3]), "r"(b0), "r"(b1));
}

__global__ __launch_bounds__(256) void gemm_bf16_kernel() {
    __shared__ __align__(16) __nv_bfloat16 sA[128 * ASTRIDE];  // 10240 B
    __shared__ __align__(16) __nv_bfloat16 sB[32 * BSTRIDE];   //  4608 B

    const int tid = threadIdx.x;
    const int lane = tid & 31;
    const int wid = tid >> 5;
    const int wm = wid & 3;        // 4 M-warps of 32 rows
    const int wn = wid >> 2;       // 2 N-warps of 32 cols
    const int mb = blockIdx.x * 128;
    const int nb = blockIdx.y * 64;
    const int lrow = lane & 15;
    const int lcol8 = (lane >> 4) << 3;   // 0 or 8 (bf16 elements)

    float acc[2][4][4];
#pragma unroll
    for (int i = 0; i < 2; i++)
#pragma unroll
        for (int j = 0; j < 4; j++)
#pragma unroll
            for (int k = 0; k < 4; k++) acc[i][j][k] = 0.f;

#pragma unroll 1
    for (int seg = 0; seg < 3; seg++) {
        const __nv_bfloat16* Ag = (seg == 2) ? g_xlo : g_xhi;
        const __nv_bfloat16* Bg = (seg == 1) ? g_Wlo : g_Whi;
#pragma unroll 1
        for (int kt = 0; kt < IN_F; kt += 32) {
            // A tile: 128 rows x 32 bf16 = 512 x 16B chunks, 2 per thread
#pragma unroll
            for (int i = 0; i < 2; i++) {
                int c = tid + i * 256;
                int r = c >> 2, c16 = c & 3;
                int grow = mb + r;
                uint4 v = make_uint4(0, 0, 0, 0);
                if (grow < N_NODES)
                    v = *(const uint4*)(Ag + (size_t)grow * IN_F + kt + c16 * 8);
                *(uint4*)(sA + r * ASTRIDE + c16 * 8) = v;
            }
            // B tile: 32 rows x 64 bf16 = 256 x 16B chunks, 1 per thread
            {
                int r = tid >> 3, c16 = tid & 7;
                uint4 v = *(const uint4*)(Bg + (size_t)(kt + r) * HF + nb + c16 * 8);
                *(uint4*)(sB + r * BSTRIDE + c16 * 8) = v;
            }
            __syncthreads();

            uint32_t a[2][2][4], b[2][2][4];
#pragma unroll
            for (int mt = 0; mt < 2; mt++)
#pragma unroll
                for (int kc = 0; kc < 2; kc++)
                    ldsm4(a[mt][kc],
                          sA + (wm * 32 + mt * 16 + lrow) * ASTRIDE + kc * 16 + lcol8);
#pragma unroll
            for (int kc = 0; kc < 2; kc++)
#pragma unroll
                for (int nt2 = 0; nt2 < 2; nt2++)
                    ldsm4t(b[kc][nt2],
                           sB + (kc * 16 + lrow) * BSTRIDE + wn * 32 + nt2 * 16 + lcol8);
#pragma unroll
            for (int mt = 0; mt < 2; mt++)
#pragma unroll
                for (int nt = 0; nt < 4; nt++)
#pragma unroll
                    for (int kc = 0; kc < 2; kc++) {
                        uint32_t* bb = &b[kc][nt >> 1][(nt & 1) * 2];
                        mma16816(acc[mt][nt], a[mt][kc], bb[0], bb[1]);
                    }
            __syncthreads();
        }
    }

    // epilogue: c0,c1 -> row (lane>>2), cols col..col+1; c2,c3 -> row+8
#pragma unroll
    for (int mt = 0; mt < 2; mt++) {
        int row0 = mb + wm * 32 + mt * 16 + (lane >> 2);
#pragma unroll
        for (int nt = 0; nt < 4; nt++) {
            int col = nb + wn * 32 + nt * 8 + (lane & 3) * 2;
            if (row0 < N_NODES)
                *(float2*)(g_h + (size_t)row0 * HF + col) =
                    make_float2(acc[mt][nt][0], acc[mt][nt][1]);
            if (row0 + 8 < N_NODES)
                *(float2*)(g_h + (size_t)(row0 + 8) * HF + col) =
                    make_float2(acc[mt][nt][2], acc[mt][nt][3]);
        }
    }
}

// ---------------- per-node attention halves: a_src, a_dst (proven in R3) ----
__global__ void att_kernel(const float* __restrict__ att_s,
                           const float* __restrict__ att_d) {
    int gw = (blockIdx.x * blockDim.x + threadIdx.x) >> 5;
    int lane = threadIdx.x & 31;
    if (gw >= N_NODES) return;
    const float* hr = g_h + (size_t)gw * HF;
#pragma unroll
    for (int hd = 0; hd < HEADS; hd++) {
        float v0 = hr[hd * 64 + lane];
        float v1 = hr[hd * 64 + 32 + lane];
        float s = v0 * att_s[hd * 64 + lane] + v1 * att_s[hd * 64 + 32 + lane];
        float d = v0 * att_d[hd * 64 + lane] + v1 * att_d[hd * 64 + 32 + lane];
#pragma unroll
        for (int o = 16; o; o >>= 1) {
            s += __shfl_xor_sync(0xffffffffu, s, o);
            d += __shfl_xor_sync(0xffffffffu, d, o);
        }
        if (lane == 0) {
            g_asrc[gw * HEADS + hd] = s;
            g_adst[gw * HEADS + hd] = d;
        }
    }
}

// ---------------- CSR build (edge_index is int32: JAX x64 is disabled) ------
__global__ void zero_deg_kernel() {
    int i = blockIdx.x * blockDim.x + threadIdx.x;
    if (i < N_NODES) g_deg[i] = 0;
}

__global__ void hist_kernel(const int* __restrict__ ei) {
    int e = blockIdx.x * blockDim.x + threadIdx.x;
    if (e >= N_EDGES) return;
    int d = ei[N_EDGES + e];
    if ((unsigned)d < N_NODES) atomicAdd(&g_deg[d], 1);
}

__global__ __launch_bounds__(SCAN_CHUNK) void blockred_kernel() {
    __shared__ int sh[SCAN_CHUNK];
    int i = blockIdx.x * SCAN_CHUNK + threadIdx.x;
    int v = (i < N_NODES) ? g_deg[i] : 0;
    sh[threadIdx.x] = v;
    __syncthreads();
#pragma unroll
    for (int off = SCAN_CHUNK / 2; off >= 32; off >>= 1) {
        if (threadIdx.x < off) sh[threadIdx.x] += sh[threadIdx.x + off];
        __syncthreads();
    }
    if (threadIdx.x < 32) {
        int s = sh[threadIdx.x];
#pragma unroll
        for (int o = 16; o; o >>= 1) s += __shfl_xor_sync(0xffffffffu, s, o);
        if (threadIdx.x == 0) g_bsum[blockIdx.x] = s;
    }
}

__global__ __launch_bounds__(128) void scanblk_kernel() {
    __shared__ int sh[128];
    int tid = threadIdx.x;
    int v = (tid < NBLK) ? g_bsum[tid] : 0;
    sh[tid] = v;
    __syncthreads();
#pragma unroll
    for (int off = 1; off < 128; off <<= 1) {
        int t = sh[tid];
        if (tid >= off) t += sh[tid - off];
        __syncthreads();
        sh[tid] = t;
        __syncthreads();
    }
    if (tid < NBLK) g_boff[tid] = sh[tid] - v;     // exclusive
    if (tid == 0) g_off[N_NODES] = sh[NBLK - 1];   // total
}

__global__ __launch_bounds__(SCAN_CHUNK) void offsets_kernel() {
    __shared__ int sh[SCAN_CHUNK];
    int tid = threadIdx.x;
    int i = blockIdx.x * SCAN_CHUNK + tid;
    int v = (i < N_NODES) ? g_deg[i] : 0;
    sh[tid] = v;
    __syncthreads();
#pragma unroll
    for (int off = 1; off < SCAN_CHUNK; off <<= 1) {
        int t = sh[tid];
        if (tid >= off) t += sh[tid - off];
        __syncthreads();
        sh[tid] = t;
        __syncthreads();
    }
    if (i < N_NODES) {
        int excl = g_boff[blockIdx.x] + sh[tid] - v;
        g_off[i] = excl;
        g_cursor[i] = excl;
    }
}

__global__ void scatter_kernel(const int* __restrict__ ei) {
    int e = blockIdx.x * blockDim.x + threadIdx.x;
    if (e >= N_EDGES) return;
    int s = ei[e];
    int d = ei[N_EDGES + e];
    if ((unsigned)d >= N_NODES || (unsigned)s >= N_NODES) return;
    int pos = atomicAdd(&g_cursor[d], 1);
    g_csr[pos] = s;
}

// Canonicalize each segment so fp32 accumulation order is deterministic.
__global__ void sortseg_kernel() {
    int gw = (blockIdx.x * blockDim.x + threadIdx.x) >> 5;
    int lane = threadIdx.x & 31;
    if (gw >= N_NODES) return;
    int lo = g_off[gw], hi = g_off[gw + 1];
    int len = hi - lo;
    if (len < 2) return;
    for (int pass = 0; pass < len; pass++) {
        int start = lo + (pass & 1);
        for (int i = start + 2 * lane; i + 1 < hi; i += 64) {
            int a = g_csr[i], b = g_csr[i + 1];
            if (a > b) { g_csr[i] = b; g_csr[i + 1] = a; }
        }
        __syncwarp();
    }
}

// ------- aggregation: warp per node, 4 heads fused, 2-deep SW pipeline ------
__global__ __launch_bounds__(256) void agg_kernel(const float* __restrict__ bias,
                                                  float* __restrict__ out) {
    int n = (blockIdx.x * blockDim.x + threadIdx.x) >> 5;
    int lane = threadIdx.x & 31;
    if (n >= N_NODES) return;
    int hd = lane >> 3;

    const float4* hrow = (const float4*)(g_h + (size_t)n * HF);
    float4 aA = hrow[lane * 2];
    float4 aB = hrow[lane * 2 + 1];

    float4 adv = *(const float4*)(g_adst + n * HEADS);
    float adn = (hd == 0) ? adv.x : (hd == 1) ? adv.y : (hd == 2) ? adv.z : adv.w;
    float4 asv = *(const float4*)(g_asrc + n * HEADS);
    float e0 = ((hd == 0) ? asv.x : (hd == 1) ? asv.y : (hd == 2) ? asv.z : asv.w) + adn;
    e0 = (e0 > 0.f) ? e0 : NEG_SLOPE * e0;   // self-loop seeds the state
    float m = e0, ssum = 1.0f;

    int lo = g_off[n], hi = g_off[n + 1];

    float4 av, v0, v1;
    if (lo < hi) {
        int s0 = g_csr[lo];
        av = *(const float4*)(g_asrc + s0 * HEADS);
        const float4* hs = (const float4*)(g_h + (size_t)s0 * HF);
        v0 = hs[lane * 2];
        v1 = hs[lane * 2 + 1];
    }
    for (int j = lo; j < hi; j++) {
        float4 cav = av, cv0 = v0, cv1 = v1;
        if (j + 1 < hi) {
            int s1 = g_csr[j + 1];
            av = *(const float4*)(g_asrc + s1 * HEADS);
            const float4* hs = (const float4*)(g_h + (size_t)s1 * HF);
            v0 = hs[lane * 2];
            v1 = hs[lane * 2 + 1];
        }
        float e = ((hd == 0) ? cav.x : (hd == 1) ? cav.y : (hd == 2) ? cav.z : cav.w) + adn;
        e = (e > 0.f) ? e : NEG_SLOPE * e;
        float nm = fmaxf(m, e);
        float corr = __expf(m - nm);
        float w = __expf(e - nm);
        ssum = ssum * corr + w;
        aA.x = aA.x * corr + w * cv0.x;  aA.y = aA.y * corr + w * cv0.y;
        aA.z = aA.z * corr + w * cv0.z;  aA.w = aA.w * corr + w * cv0.w;
        aB.x = aB.x * corr + w * cv1.x;  aB.y = aB.y * corr + w * cv1.y;
        aB.z = aB.z * corr + w * cv1.z;  aB.w = aB.w * corr + w * cv1.w;
        m = nm;
    }

    float inv = 1.0f / ssum;
    float4 b0 = *(const float4*)(bias + lane * 8);
    float4 b1 = *(const float4*)(bias + lane * 8 + 4);
    float4* orow = (float4*)(out + (size_t)n * HF);
    orow[lane * 2]     = make_float4(aA.x * inv + b0.x, aA.y * inv + b0.y,
                                     aA.z * inv + b0.z, aA.w * inv + b0.w);
    orow[lane * 2 + 1] = make_float4(aB.x * inv + b1.x, aB.y * inv + b1.y,
                                     aB.z * inv + b1.z, aB.w * inv + b1.w);
}

// ---------------- launch ----------------------------------------------------
extern "C" void kernel_launch(void* const* d_in, const int* in_sizes, int n_in,
                              void* d_out, int out_size) {
    const float* x     = (const float*)d_in[0];
    const int*   ei    = (const int*)d_in[1];       // int32: JAX x64 disabled
    const float* W     = (const float*)d_in[2];
    const float* att_s = (const float*)d_in[3];
    const float* att_d = (const float*)d_in[4];
    const float* bias  = (const float*)d_in[5];
    float*       out   = (float*)d_out;
    (void)in_sizes; (void)n_in; (void)out_size;

    wsplit_kernel<<<(IN_F * HF + 255) / 256, 256>>>(W);
    xsplit_kernel<<<(N_NODES * 32 + 255) / 256, 256>>>(x);
    gemm_bf16_kernel<<<dim3((N_NODES + 127) / 128, HF / 64), 256>>>();
    att_kernel<<<(N_NODES * 32 + 255) / 256, 256>>>(att_s, att_d);
    zero_deg_kernel<<<(N_NODES + 255) / 256, 256>>>();
    hist_kernel<<<(N_EDGES + 255) / 256, 256>>>(ei);
    blockred_kernel<<<NBLK, SCAN_CHUNK>>>();
    scanblk_kernel<<<1, 128>>>();
    offsets_kernel<<<NBLK, SCAN_CHUNK>>>();
    scatter_kernel<<<(N_EDGES + 255) / 256, 256>>>(ei);
    sortseg_kernel<<<(N_NODES * 32 + 255) / 256, 256>>>();
    agg_kernel<<<(N_NODES * 32 + 255) / 256, 256>>>(bias, out);
}

// round 11
// speedup vs baseline: 1.5539x; 1.0595x over previous
#include <cuda_runtime.h>
#include <cuda_bf16.h>
#include <cstdint>

#define N_NODES 50000
#define N_EDGES 800000
#define IN_F 256
#define HEADS 4
#define OUT_F 64
#define HF 256            // HEADS * OUT_F
#define NEG_SLOPE 0.2f

#define SCAN_CHUNK 512
#define NBLK ((N_NODES + SCAN_CHUNK - 1) / SCAN_CHUNK)   // 98

// ---------------- scratch (static device allocations; no cudaMalloc) --------
__device__ float g_h[(size_t)N_NODES * HF];      // 51.2 MB  projected features
__device__ __nv_bfloat16 g_xhi[(size_t)N_NODES * IN_F];   // 25.6 MB
__device__ __nv_bfloat16 g_xlo[(size_t)N_NODES * IN_F];   // 25.6 MB
__device__ __nv_bfloat16 g_Whi[IN_F * HF];
__device__ __nv_bfloat16 g_Wlo[IN_F * HF];
__device__ float g_asrc[N_NODES * HEADS];
__device__ float g_adst[N_NODES * HEADS];
__device__ int   g_deg[N_NODES];
__device__ int   g_off[N_NODES + 1];
__device__ int   g_cursor[N_NODES];
__device__ int   g_csr[N_EDGES];                 // src ids grouped by dst
__device__ int   g_bsum[NBLK];
__device__ int   g_boff[NBLK];

// ---------------- split kernels: v -> bf16 hi + bf16 residual ---------------
__global__ void wsplit_kernel(const float* __restrict__ W) {
    int i = blockIdx.x * blockDim.x + threadIdx.x;
    if (i >= IN_F * HF) return;
    float w = W[i];
    __nv_bfloat16 hi = __float2bfloat16(w);
    __nv_bfloat16 lo = __float2bfloat16(w - __bfloat162float(hi));
    g_Whi[i] = hi;
    g_Wlo[i] = lo;
}

__global__ __launch_bounds__(256) void xsplit_kernel(const float* __restrict__ x) {
    // warp per node; lane owns 8 consecutive floats
    int n = (blockIdx.x * blockDim.x + threadIdx.x) >> 5;
    int lane = threadIdx.x & 31;
    if (n >= N_NODES) return;
    const float4* xr = (const float4*)(x + (size_t)n * IN_F) + lane * 2;
    float4 xa = xr[0], xb = xr[1];
    float xs[8] = {xa.x, xa.y, xa.z, xa.w, xb.x, xb.y, xb.z, xb.w};
    union { __nv_bfloat16 b[8]; uint4 u; } H, L;
#pragma unroll
    for (int i = 0; i < 8; i++) {
        H.b[i] = __float2bfloat16(xs[i]);
        L.b[i] = __float2bfloat16(xs[i] - __bfloat162float(H.b[i]));
    }
    *(uint4*)(g_xhi + (size_t)n * IN_F + lane * 8) = H.u;
    *(uint4*)(g_xlo + (size_t)n * IN_F + lane * 8) = L.u;
}

// ---------------- GEMM: g_h = x @ W via 3 bf16 tensor-core passes -----------
// hi*hi + hi*lo + lo*hi  (lo*lo dropped, ~2^-16 relative)
// blockIdx.y = head; fused a_src/a_dst epilogue (deterministic, no atomics).
#define ASTRIDE 40   // bf16 elements per A smem row (80B, conflict-free ldmatrix)
#define BSTRIDE 72   // bf16 elements per B smem row (144B)

__device__ __forceinline__ void ldsm4(uint32_t* r, const __nv_bfloat16* p) {
    unsigned a = (unsigned)__cvta_generic_to_shared(p);
    asm volatile("ldmatrix.sync.aligned.m8n8.x4.shared.b16 {%0,%1,%2,%3}, [%4];"
                 : "=r"(r[0]), "=r"(r[1]), "=r"(r[2]), "=r"(r[3]) : "r"(a));
}
__device__ __forceinline__ void ldsm4t(uint32_t* r, const __nv_bfloat16* p) {
    unsigned a = (unsigned)__cvta_generic_to_shared(p);
    asm volatile("ldmatrix.sync.aligned.m8n8.x4.trans.shared.b16 {%0,%1,%2,%3}, [%4];"
                 : "=r"(r[0]), "=r"(r[1]), "=r"(r[2]), "=r"(r[3]) : "r"(a));
}
__device__ __forceinline__ void mma16816(float* c, const uint32_t* a, uint32_t b0, uint32_t b1) {
    asm volatile("mma.sync.aligned.m16n8k16.row.col.f32.bf16.bf16.f32 "
                 "{%0,%1,%2,%3}, {%4,%5,%6,%7}, {%8,%9}, {%0,%1,%2,%3};"
                 : "+f"(c[0]), "+f"(c[1]), "+f"(c[2]), "+f"(c[3])
                 : "r"(a[0]), "r"(a[1]), "r"(a[2]), "r"(a[3]), "r"(b0), "r"(b1));
}

__global__ __launch_bounds__(256) void gemm_bf16_kernel(const float* __restrict__ att_s,
                                                        const float* __restrict__ att_d) {
    __shared__ __align__(16) __nv_bfloat16 sA[128 * ASTRIDE];  // 10240 B
    __shared__ __align__(16) __nv_bfloat16 sB[32 * BSTRIDE];   //  4608 B
    __shared__ float sds[2][128];   // per-(wn,row) a_src partials
    __shared__ float sdd[2][128];   // per-(wn,row) a_dst partials

    const int tid = threadIdx.x;
    const int lane = tid & 31;
    const int wid = tid >> 5;
    const int wm = wid & 3;        // 4 M-warps of 32 rows
    const int wn = wid >> 2;       // 2 N-warps of 32 cols
    const int mb = blockIdx.x * 128;
    const int hd = blockIdx.y;     // head; nb = hd*64
    const int nb = hd * 64;
    const int lrow = lane & 15;
    const int lcol8 = (lane >> 4) << 3;   // 0 or 8 (bf16 elements)

    float acc[2][4][4];
#pragma unroll
    for (int i = 0; i < 2; i++)
#pragma unroll
        for (int j = 0; j < 4; j++)
#pragma unroll
            for (int k = 0; k < 4; k++) acc[i][j][k] = 0.f;

#pragma unroll 1
    for (int seg = 0; seg < 3; seg++) {
        const __nv_bfloat16* Ag = (seg == 2) ? g_xlo : g_xhi;
        const __nv_bfloat16* Bg = (seg == 1) ? g_Wlo : g_Whi;
#pragma unroll 1
        for (int kt = 0; kt < IN_F; kt += 32) {
            // A tile: 128 rows x 32 bf16 = 512 x 16B chunks, 2 per thread
#pragma unroll
            for (int i = 0; i < 2; i++) {
                int c = tid + i * 256;
                int r = c >> 2, c16 = c & 3;
                int grow = mb + r;
                uint4 v = make_uint4(0, 0, 0, 0);
                if (grow < N_NODES)
                    v = *(const uint4*)(Ag + (size_t)grow * IN_F + kt + c16 * 8);
                *(uint4*)(sA + r * ASTRIDE + c16 * 8) = v;
            }
            // B tile: 32 rows x 64 bf16 = 256 x 16B chunks, 1 per thread
            {
                int r = tid >> 3, c16 = tid & 7;
                uint4 v = *(const uint4*)(Bg + (size_t)(kt + r) * HF + nb + c16 * 8);
                *(uint4*)(sB + r * BSTRIDE + c16 * 8) = v;
            }
            __syncthreads();

            uint32_t a[2][2][4], b[2][2][4];
#pragma unroll
            for (int mt = 0; mt < 2; mt++)
#pragma unroll
                for (int kc = 0; kc < 2; kc++)
                    ldsm4(a[mt][kc],
                          sA + (wm * 32 + mt * 16 + lrow) * ASTRIDE + kc * 16 + lcol8);
#pragma unroll
            for (int kc = 0; kc < 2; kc++)
#pragma unroll
                for (int nt2 = 0; nt2 < 2; nt2++)
                    ldsm4t(b[kc][nt2],
                           sB + (kc * 16 + lrow) * BSTRIDE + wn * 32 + nt2 * 16 + lcol8);
#pragma unroll
            for (int mt = 0; mt < 2; mt++)
#pragma unroll
                for (int nt = 0; nt < 4; nt++)
#pragma unroll
                    for (int kc = 0; kc < 2; kc++) {
                        uint32_t* bb = &b[kc][nt >> 1][(nt & 1) * 2];
                        mma16816(acc[mt][nt], a[mt][kc], bb[0], bb[1]);
                    }
            __syncthreads();
        }
    }

    // ---- epilogue: store g_h + fused attention dots ----
    const float* wsp = att_s + hd * OUT_F;
    const float* wdp = att_d + hd * OUT_F;

#pragma unroll
    for (int mt = 0; mt < 2; mt++) {
        int row0 = mb + wm * 32 + mt * 16 + (lane >> 2);
        float s0 = 0.f, s1 = 0.f, d0 = 0.f, d1 = 0.f;
#pragma unroll
        for (int nt = 0; nt < 4; nt++) {
            int col = nb + wn * 32 + nt * 8 + (lane & 3) * 2;
            if (row0 < N_NODES)
                *(float2*)(g_h + (size_t)row0 * HF + col) =
                    make_float2(acc[mt][nt][0], acc[mt][nt][1]);
            if (row0 + 8 < N_NODES)
                *(float2*)(g_h + (size_t)(row0 + 8) * HF + col) =
                    make_float2(acc[mt][nt][2], acc[mt][nt][3]);
            int wc = wn * 32 + nt * 8 + (lane & 3) * 2;   // col within head
            float w0 = wsp[wc], w1 = wsp[wc + 1];
            float u0 = wdp[wc], u1 = wdp[wc + 1];
            s0 += acc[mt][nt][0] * w0 + acc[mt][nt][1] * w1;
            d0 += acc[mt][nt][0] * u0 + acc[mt][nt][1] * u1;
            s1 += acc[mt][nt][2] * w0 + acc[mt][nt][3] * w1;
            d1 += acc[mt][nt][2] * u0 + acc[mt][nt][3] * u1;
        }
        // quad reduce (lanes lane^1, lane^2 share the same row)
#pragma unroll
        for (int o = 1; o <= 2; o <<= 1) {
            s0 += __shfl_xor_sync(0xffffffffu, s0, o);
            s1 += __shfl_xor_sync(0xffffffffu, s1, o);
            d0 += __shfl_xor_sync(0xffffffffu, d0, o);
            d1 += __shfl_xor_sync(0xffffffffu, d1, o);
        }
        if ((lane & 3) == 0) {            // unique writer per (wn, local row)
            int lr = wm * 32 + mt * 16 + (lane >> 2);
            sds[wn][lr] = s0;  sdd[wn][lr] = d0;
            sds[wn][lr + 8] = s1;  sdd[wn][lr + 8] = d1;
        }
    }
    __syncthreads();
    if (tid < 128) {                      // fixed-order sum: deterministic
        int grow = mb + tid;
        if (grow < N_NODES) {
            g_asrc[grow * HEADS + hd] = sds[0][tid] + sds[1][tid];
            g_adst[grow * HEADS + hd] = sdd[0][tid] + sdd[1][tid];
        }
    }
}

// ---------------- CSR build (edge_index is int32: JAX x64 is disabled) ------
__global__ void zero_deg_kernel() {
    int i = blockIdx.x * blockDim.x + threadIdx.x;
    if (i < N_NODES) g_deg[i] = 0;
}

__global__ void hist_kernel(const int* __restrict__ ei) {
    int e = blockIdx.x * blockDim.x + threadIdx.x;
    if (e >= N_EDGES) return;
    int d = ei[N_EDGES + e];
    if ((unsigned)d < N_NODES) atomicAdd(&g_deg[d], 1);
}

__global__ __launch_bounds__(SCAN_CHUNK) void blockred_kernel() {
    __shared__ int sh[SCAN_CHUNK];
    int i = blockIdx.x * SCAN_CHUNK + threadIdx.x;
    int v = (i < N_NODES) ? g_deg[i] : 0;
    sh[threadIdx.x] = v;
    __syncthreads();
#pragma unroll
    for (int off = SCAN_CHUNK / 2; off >= 32; off >>= 1) {
        if (threadIdx.x < off) sh[threadIdx.x] += sh[threadIdx.x + off];
        __syncthreads();
    }
    if (threadIdx.x < 32) {
        int s = sh[threadIdx.x];
#pragma unroll
        for (int o = 16; o; o >>= 1) s += __shfl_xor_sync(0xffffffffu, s, o);
        if (threadIdx.x == 0) g_bsum[blockIdx.x] = s;
    }
}

__global__ __launch_bounds__(128) void scanblk_kernel() {
    __shared__ int sh[128];
    int tid = threadIdx.x;
    int v = (tid < NBLK) ? g_bsum[tid] : 0;
    sh[tid] = v;
    __syncthreads();
#pragma unroll
    for (int off = 1; off < 128; off <<= 1) {
        int t = sh[tid];
        if (tid >= off) t += sh[tid - off];
        __syncthreads();
        sh[tid] = t;
        __syncthreads();
    }
    if (tid < NBLK) g_boff[tid] = sh[tid] - v;     // exclusive
    if (tid == 0) g_off[N_NODES] = sh[NBLK - 1];   // total
}

__global__ __launch_bounds__(SCAN_CHUNK) void offsets_kernel() {
    __shared__ int sh[SCAN_CHUNK];
    int tid = threadIdx.x;
    int i = blockIdx.x * SCAN_CHUNK + tid;
    int v = (i < N_NODES) ? g_deg[i] : 0;
    sh[tid] = v;
    __syncthreads();
#pragma unroll
    for (int off = 1; off < SCAN_CHUNK; off <<= 1) {
        int t = sh[tid];
        if (tid >= off) t += sh[tid - off];
        __syncthreads();
        sh[tid] = t;
        __syncthreads();
    }
    if (i < N_NODES) {
        int excl = g_boff[blockIdx.x] + sh[tid] - v;
        g_off[i] = excl;
        g_cursor[i] = excl;
    }
}

__global__ void scatter_kernel(const int* __restrict__ ei) {
    int e = blockIdx.x * blockDim.x + threadIdx.x;
    if (e >= N_EDGES) return;
    int s = ei[e];
    int d = ei[N_EDGES + e];
    if ((unsigned)d >= N_NODES || (unsigned)s >= N_NODES) return;
    int pos = atomicAdd(&g_cursor[d], 1);
    g_csr[pos] = s;
}

// Canonicalize each segment so fp32 accumulation order is deterministic.
__global__ void sortseg_kernel() {
    int gw = (blockIdx.x * blockDim.x + threadIdx.x) >> 5;
    int lane = threadIdx.x & 31;
    if (gw >= N_NODES) return;
    int lo = g_off[gw], hi = g_off[gw + 1];
    int len = hi - lo;
    if (len < 2) return;
    for (int pass = 0; pass < len; pass++) {
        int start = lo + (pass & 1);
        for (int i = start + 2 * lane; i + 1 < hi; i += 64) {
            int a = g_csr[i], b = g_csr[i + 1];
            if (a > b) { g_csr[i] = b; g_csr[i + 1] = a; }
        }
        __syncwarp();
    }
}

// ------- aggregation: warp per node, 4 heads fused, 2-deep SW pipeline ------
__global__ __launch_bounds__(256) void agg_kernel(const float* __restrict__ bias,
                                                  float* __restrict__ out) {
    int n = (blockIdx.x * blockDim.x + threadIdx.x) >> 5;
    int lane = threadIdx.x & 31;
    if (n >= N_NODES) return;
    int hd = lane >> 3;

    const float4* hrow = (const float4*)(g_h + (size_t)n * HF);
    float4 aA = hrow[lane * 2];
    float4 aB = hrow[lane * 2 + 1];

    float4 adv = *(const float4*)(g_adst + n * HEADS);
    float adn = (hd == 0) ? adv.x : (hd == 1) ? adv.y : (hd == 2) ? adv.z : adv.w;
    float4 asv = *(const float4*)(g_asrc + n * HEADS);
    float e0 = ((hd == 0) ? asv.x : (hd == 1) ? asv.y : (hd == 2) ? asv.z : asv.w) + adn;
    e0 = (e0 > 0.f) ? e0 : NEG_SLOPE * e0;   // self-loop seeds the state
    float m = e0, ssum = 1.0f;

    int lo = g_off[n], hi = g_off[n + 1];

    float4 av, v0, v1;
    if (lo < hi) {
        int s0 = g_csr[lo];
        av = *(const float4*)(g_asrc + s0 * HEADS);
        const float4* hs = (const float4*)(g_h + (size_t)s0 * HF);
        v0 = hs[lane * 2];
        v1 = hs[lane * 2 + 1];
    }
    for (int j = lo; j < hi; j++) {
        float4 cav = av, cv0 = v0, cv1 = v1;
        if (j + 1 < hi) {
            int s1 = g_csr[j + 1];
            av = *(const float4*)(g_asrc + s1 * HEADS);
            const float4* hs = (const float4*)(g_h + (size_t)s1 * HF);
            v0 = hs[lane * 2];
            v1 = hs[lane * 2 + 1];
        }
        float e = ((hd == 0) ? cav.x : (hd == 1) ? cav.y : (hd == 2) ? cav.z : cav.w) + adn;
        e = (e > 0.f) ? e : NEG_SLOPE * e;
        float nm = fmaxf(m, e);
        float corr = __expf(m - nm);
        float w = __expf(e - nm);
        ssum = ssum * corr + w;
        aA.x = aA.x * corr + w * cv0.x;  aA.y = aA.y * corr + w * cv0.y;
        aA.z = aA.z * corr + w * cv0.z;  aA.w = aA.w * corr + w * cv0.w;
        aB.x = aB.x * corr + w * cv1.x;  aB.y = aB.y * corr + w * cv1.y;
        aB.z = aB.z * corr + w * cv1.z;  aB.w = aB.w * corr + w * cv1.w;
        m = nm;
    }

    float inv = 1.0f / ssum;
    float4 b0 = *(const float4*)(bias + lane * 8);
    float4 b1 = *(const float4*)(bias + lane * 8 + 4);
    float4* orow = (float4*)(out + (size_t)n * HF);
    orow[lane * 2]     = make_float4(aA.x * inv + b0.x, aA.y * inv + b0.y,
                                     aA.z * inv + b0.z, aA.w * inv + b0.w);
    orow[lane * 2 + 1] = make_float4(aB.x * inv + b1.x, aB.y * inv + b1.y,
                                     aB.z * inv + b1.z, aB.w * inv + b1.w);
}

// ---------------- launch ----------------------------------------------------
extern "C" void kernel_launch(void* const* d_in, const int* in_sizes, int n_in,
                              void* d_out, int out_size) {
    const float* x     = (const float*)d_in[0];
    const int*   ei    = (const int*)d_in[1];       // int32: JAX x64 disabled
    const float* W     = (const float*)d_in[2];
    const float* att_s = (const float*)d_in[3];
    const float* att_d = (const float*)d_in[4];
    const float* bias  = (const float*)d_in[5];
    float*       out   = (float*)d_out;
    (void)in_sizes; (void)n_in; (void)out_size;

    wsplit_kernel<<<(IN_F * HF + 255) / 256, 256>>>(W);
    xsplit_kernel<<<(N_NODES * 32 + 255) / 256, 256>>>(x);
    gemm_bf16_kernel<<<dim3((N_NODES + 127) / 128, HF / 64), 256>>>(att_s, att_d);
    zero_deg_kernel<<<(N_NODES + 255) / 256, 256>>>();
    hist_kernel<<<(N_EDGES + 255) / 256, 256>>>(ei);
    blockred_kernel<<<NBLK, SCAN_CHUNK>>>();
    scanblk_kernel<<<1, 128>>>();
    offsets_kernel<<<NBLK, SCAN_CHUNK>>>();
    scatter_kernel<<<(N_EDGES + 255) / 256, 256>>>(ei);
    sortseg_kernel<<<(N_NODES * 32 + 255) / 256, 256>>>();
    agg_kernel<<<(N_NODES * 32 + 255) / 256, 256>>>(bias, out);
}